// round 4
// baseline (speedup 1.0000x reference)
#include <cuda_runtime.h>

#define Nn 8192
#define FIN 512
#define FOUT 256
#define ALPHA 0.2f
#define NEG_PAD (-2147483648.0f)

// scratch (no allocations allowed)
__device__ __align__(16) float g_v1[FIN];
__device__ __align__(16) float g_v2[FIN];
__device__ __align__(16) float g_s1[Nn];
__device__ __align__(16) float g_s2[Nn];

// Kernel 1: v1[k] = sum_f W[k][f]*a[f], v2[k] = sum_f W[k][f]*a[FOUT+f]
__global__ void compute_v_kernel(const float* __restrict__ W,
                                 const float* __restrict__ a) {
    int k = blockIdx.x * blockDim.x + threadIdx.x;
    if (k >= FIN) return;
    const float* wrow = W + (size_t)k * FOUT;
    float acc1 = 0.f, acc2 = 0.f;
#pragma unroll 8
    for (int f = 0; f < FOUT; f++) {
        float w = wrow[f];
        acc1 = fmaf(w, a[f], acc1);
        acc2 = fmaf(w, a[FOUT + f], acc2);
    }
    g_v1[k] = acc1;
    g_v2[k] = acc2;
}

// Kernel 2: warp per row: s1[i] = h[i].v1, s2[i] = h[i].v2
__global__ void compute_s_kernel(const float* __restrict__ h) {
    int warp = (blockIdx.x * blockDim.x + threadIdx.x) >> 5;
    int lane = threadIdx.x & 31;
    if (warp >= Nn) return;
    const float* hrow = h + (size_t)warp * FIN;
    float acc1 = 0.f, acc2 = 0.f;
#pragma unroll
    for (int k = lane; k < FIN; k += 32) {
        float x = hrow[k];
        acc1 = fmaf(x, g_v1[k], acc1);
        acc2 = fmaf(x, g_v2[k], acc2);
    }
#pragma unroll
    for (int o = 16; o; o >>= 1) {
        acc1 += __shfl_xor_sync(0xffffffffu, acc1, o);
        acc2 += __shfl_xor_sync(0xffffffffu, acc2, o);
    }
    if (lane == 0) {
        g_s1[warp] = acc1;
        g_s2[warp] = acc2;
    }
}

// Kernel 3: one block per row. Stream the adj row once (int4, evict-first),
// keep the 16 per-thread scores register-resident across both reductions,
// write float4 with streaming stores.
__global__ __launch_bounds__(512) void attn_softmax_kernel(
    const int* __restrict__ adj, float* __restrict__ out) {
    __shared__ float red[32];

    const int row = blockIdx.x;
    const int t = threadIdx.x;
    const int wid = t >> 5;
    const int lane = t & 31;

    const float s1 = g_s1[row];
    const int4* adjrow = reinterpret_cast<const int4*>(adj + (size_t)row * Nn);
    const float4* s2v4 = reinterpret_cast<const float4*>(g_s2);

    // Pass A: load adj (streaming) + s2, compute masked leaky-relu scores
    float4 ev[4];
    float lmax = NEG_PAD;
#pragma unroll
    for (int k = 0; k < 4; k++) {
        int i4 = t + k * 512;
        int4 av = __ldcs(&adjrow[i4]);
        float4 sv = s2v4[i4];
        float e0 = s1 + sv.x; e0 = (e0 > 0.f) ? e0 : ALPHA * e0; e0 = (av.x > 0) ? e0 : NEG_PAD;
        float e1 = s1 + sv.y; e1 = (e1 > 0.f) ? e1 : ALPHA * e1; e1 = (av.y > 0) ? e1 : NEG_PAD;
        float e2 = s1 + sv.z; e2 = (e2 > 0.f) ? e2 : ALPHA * e2; e2 = (av.z > 0) ? e2 : NEG_PAD;
        float e3 = s1 + sv.w; e3 = (e3 > 0.f) ? e3 : ALPHA * e3; e3 = (av.w > 0) ? e3 : NEG_PAD;
        ev[k].x = e0; ev[k].y = e1; ev[k].z = e2; ev[k].w = e3;
        lmax = fmaxf(lmax, fmaxf(fmaxf(e0, e1), fmaxf(e2, e3)));
    }

    // Block max reduction (16 warps)
#pragma unroll
    for (int o = 16; o; o >>= 1)
        lmax = fmaxf(lmax, __shfl_xor_sync(0xffffffffu, lmax, o));
    if (lane == 0) red[wid] = lmax;
    __syncthreads();
    if (t < 32) {
        float m = (t < 16) ? red[t] : NEG_PAD;
#pragma unroll
        for (int o = 16; o; o >>= 1)
            m = fmaxf(m, __shfl_xor_sync(0xffffffffu, m, o));
        if (t == 0) red[0] = m;
    }
    __syncthreads();
    const float rmax = red[0];
    __syncthreads();   // protect red[0] before sum reduction overwrites it

    // Pass B: exp in registers + local sum
    float lsum = 0.f;
#pragma unroll
    for (int k = 0; k < 4; k++) {
        ev[k].x = __expf(ev[k].x - rmax);
        ev[k].y = __expf(ev[k].y - rmax);
        ev[k].z = __expf(ev[k].z - rmax);
        ev[k].w = __expf(ev[k].w - rmax);
        lsum += (ev[k].x + ev[k].y) + (ev[k].z + ev[k].w);
    }

    // Block sum reduction
#pragma unroll
    for (int o = 16; o; o >>= 1)
        lsum += __shfl_xor_sync(0xffffffffu, lsum, o);
    if (lane == 0) red[wid] = lsum;
    __syncthreads();
    if (t < 32) {
        float s = (t < 16) ? red[t] : 0.f;
#pragma unroll
        for (int o = 16; o; o >>= 1)
            s += __shfl_xor_sync(0xffffffffu, s, o);
        if (t == 0) red[0] = s;
    }
    __syncthreads();
    const float inv = 1.0f / red[0];

    // Pass C: normalized write straight from registers (streaming stores)
    float4* orow = reinterpret_cast<float4*>(out + (size_t)row * Nn);
#pragma unroll
    for (int k = 0; k < 4; k++) {
        int i4 = t + k * 512;
        float4 v = ev[k];
        v.x *= inv; v.y *= inv; v.z *= inv; v.w *= inv;
        __stcs(&orow[i4], v);
    }
}

extern "C" void kernel_launch(void* const* d_in, const int* in_sizes, int n_in,
                              void* d_out, int out_size) {
    const float* h   = (const float*)d_in[0];
    const int*   adj = (const int*)d_in[1];
    const float* W   = (const float*)d_in[2];
    const float* a   = (const float*)d_in[3];
    float* out = (float*)d_out;

    compute_v_kernel<<<1, FIN>>>(W, a);
    compute_s_kernel<<<Nn / 8, 256>>>(h);          // 8 warps/block, warp per row
    attn_softmax_kernel<<<Nn, 512>>>(adj, out);
}

// round 8
// speedup vs baseline: 1.6443x; 1.6443x over previous
#include <cuda_runtime.h>

#define Nn 8192
#define FIN 512
#define FOUT 256
#define ALPHA 0.2f
#define NEG_PAD (-2147483648.0f)

// scratch (no allocations allowed)
__device__ __align__(16) float g_v1[FIN];
__device__ __align__(16) float g_v2[FIN];
__device__ __align__(16) float g_s1[Nn];
__device__ __align__(16) float g_s2[Nn];

// Kernel 1: one warp per k: v1[k] = sum_f W[k][f]*a[f], v2[k] likewise.
// 64 blocks x 256 threads = 512 warps = FIN. Coalesced W row reads.
__global__ void compute_v_kernel(const float* __restrict__ W,
                                 const float* __restrict__ a) {
    int k = (blockIdx.x * blockDim.x + threadIdx.x) >> 5;
    int lane = threadIdx.x & 31;
    if (k >= FIN) return;
    const float* wrow = W + (size_t)k * FOUT;
    float acc1 = 0.f, acc2 = 0.f;
#pragma unroll
    for (int f = lane; f < FOUT; f += 32) {
        float w = wrow[f];
        acc1 = fmaf(w, a[f], acc1);
        acc2 = fmaf(w, a[FOUT + f], acc2);
    }
#pragma unroll
    for (int o = 16; o; o >>= 1) {
        acc1 += __shfl_xor_sync(0xffffffffu, acc1, o);
        acc2 += __shfl_xor_sync(0xffffffffu, acc2, o);
    }
    if (lane == 0) {
        g_v1[k] = acc1;
        g_v2[k] = acc2;
    }
}

// Kernel 2: warp per row: s1[i] = h[i].v1, s2[i] = h[i].v2
__global__ void compute_s_kernel(const float* __restrict__ h) {
    int warp = (blockIdx.x * blockDim.x + threadIdx.x) >> 5;
    int lane = threadIdx.x & 31;
    if (warp >= Nn) return;
    const float* hrow = h + (size_t)warp * FIN;
    float acc1 = 0.f, acc2 = 0.f;
#pragma unroll
    for (int k = lane; k < FIN; k += 32) {
        float x = hrow[k];
        acc1 = fmaf(x, g_v1[k], acc1);
        acc2 = fmaf(x, g_v2[k], acc2);
    }
#pragma unroll
    for (int o = 16; o; o >>= 1) {
        acc1 += __shfl_xor_sync(0xffffffffu, acc1, o);
        acc2 += __shfl_xor_sync(0xffffffffu, acc2, o);
    }
    if (lane == 0) {
        g_s1[warp] = acc1;
        g_s2[warp] = acc2;
    }
}

// Kernel 3: one block per row. Stream the adj row once (int4, evict-first),
// keep the 16 per-thread scores register-resident across both reductions,
// write float4 with streaming stores.
__global__ __launch_bounds__(512) void attn_softmax_kernel(
    const int* __restrict__ adj, float* __restrict__ out) {
    __shared__ float red[32];

    const int row = blockIdx.x;
    const int t = threadIdx.x;
    const int wid = t >> 5;
    const int lane = t & 31;

    const float s1 = g_s1[row];
    const int4* adjrow = reinterpret_cast<const int4*>(adj + (size_t)row * Nn);
    const float4* s2v4 = reinterpret_cast<const float4*>(g_s2);

    // Pass A: load adj (streaming) + s2, compute masked leaky-relu scores
    float4 ev[4];
    float lmax = NEG_PAD;
#pragma unroll
    for (int k = 0; k < 4; k++) {
        int i4 = t + k * 512;
        int4 av = __ldcs(&adjrow[i4]);
        float4 sv = s2v4[i4];
        float e0 = s1 + sv.x; e0 = (e0 > 0.f) ? e0 : ALPHA * e0; e0 = (av.x > 0) ? e0 : NEG_PAD;
        float e1 = s1 + sv.y; e1 = (e1 > 0.f) ? e1 : ALPHA * e1; e1 = (av.y > 0) ? e1 : NEG_PAD;
        float e2 = s1 + sv.z; e2 = (e2 > 0.f) ? e2 : ALPHA * e2; e2 = (av.z > 0) ? e2 : NEG_PAD;
        float e3 = s1 + sv.w; e3 = (e3 > 0.f) ? e3 : ALPHA * e3; e3 = (av.w > 0) ? e3 : NEG_PAD;
        ev[k].x = e0; ev[k].y = e1; ev[k].z = e2; ev[k].w = e3;
        lmax = fmaxf(lmax, fmaxf(fmaxf(e0, e1), fmaxf(e2, e3)));
    }

    // Block max reduction (16 warps)
#pragma unroll
    for (int o = 16; o; o >>= 1)
        lmax = fmaxf(lmax, __shfl_xor_sync(0xffffffffu, lmax, o));
    if (lane == 0) red[wid] = lmax;
    __syncthreads();
    if (t < 32) {
        float m = (t < 16) ? red[t] : NEG_PAD;
#pragma unroll
        for (int o = 16; o; o >>= 1)
            m = fmaxf(m, __shfl_xor_sync(0xffffffffu, m, o));
        if (t == 0) red[0] = m;
    }
    __syncthreads();
    const float rmax = red[0];
    __syncthreads();   // protect red[0] before sum reduction overwrites it

    // Pass B: exp in registers + local sum
    float lsum = 0.f;
#pragma unroll
    for (int k = 0; k < 4; k++) {
        ev[k].x = __expf(ev[k].x - rmax);
        ev[k].y = __expf(ev[k].y - rmax);
        ev[k].z = __expf(ev[k].z - rmax);
        ev[k].w = __expf(ev[k].w - rmax);
        lsum += (ev[k].x + ev[k].y) + (ev[k].z + ev[k].w);
    }

    // Block sum reduction
#pragma unroll
    for (int o = 16; o; o >>= 1)
        lsum += __shfl_xor_sync(0xffffffffu, lsum, o);
    if (lane == 0) red[wid] = lsum;
    __syncthreads();
    if (t < 32) {
        float s = (t < 16) ? red[t] : 0.f;
#pragma unroll
        for (int o = 16; o; o >>= 1)
            s += __shfl_xor_sync(0xffffffffu, s, o);
        if (t == 0) red[0] = s;
    }
    __syncthreads();
    const float inv = 1.0f / red[0];

    // Pass C: normalized write straight from registers (streaming stores)
    float4* orow = reinterpret_cast<float4*>(out + (size_t)row * Nn);
#pragma unroll
    for (int k = 0; k < 4; k++) {
        int i4 = t + k * 512;
        float4 v = ev[k];
        v.x *= inv; v.y *= inv; v.z *= inv; v.w *= inv;
        __stcs(&orow[i4], v);
    }
}

extern "C" void kernel_launch(void* const* d_in, const int* in_sizes, int n_in,
                              void* d_out, int out_size) {
    const float* h   = (const float*)d_in[0];
    const int*   adj = (const int*)d_in[1];
    const float* W   = (const float*)d_in[2];
    const float* a   = (const float*)d_in[3];
    float* out = (float*)d_out;

    compute_v_kernel<<<FIN / 8, 256>>>(W, a);      // warp per k, 64 blocks
    compute_s_kernel<<<Nn / 8, 256>>>(h);          // 8 warps/block, warp per row
    attn_softmax_kernel<<<Nn, 512>>>(adj, out);
}

// round 12
// speedup vs baseline: 1.7158x; 1.0435x over previous
#include <cuda_runtime.h>

#define Nn 8192
#define FIN 512
#define FOUT 256
#define ALPHA 0.2f

// scratch (no allocations allowed)
__device__ __align__(16) float g_v1[FIN];
__device__ __align__(16) float g_v2[FIN];
__device__ __align__(16) float g_s1[Nn];
__device__ __align__(16) float g_s2[Nn];
__device__ float g_s2max;

// Kernel 1: one warp per k: v1[k] = sum_f W[k][f]*a[f], v2[k] likewise.
__global__ void compute_v_kernel(const float* __restrict__ W,
                                 const float* __restrict__ a) {
    int k = (blockIdx.x * blockDim.x + threadIdx.x) >> 5;
    int lane = threadIdx.x & 31;
    if (k >= FIN) return;
    const float* wrow = W + (size_t)k * FOUT;
    float acc1 = 0.f, acc2 = 0.f;
#pragma unroll
    for (int f = lane; f < FOUT; f += 32) {
        float w = wrow[f];
        acc1 = fmaf(w, a[f], acc1);
        acc2 = fmaf(w, a[FOUT + f], acc2);
    }
#pragma unroll
    for (int o = 16; o; o >>= 1) {
        acc1 += __shfl_xor_sync(0xffffffffu, acc1, o);
        acc2 += __shfl_xor_sync(0xffffffffu, acc2, o);
    }
    if (lane == 0) {
        g_v1[k] = acc1;
        g_v2[k] = acc2;
    }
}

// Kernel 2: warp per row: s1[i] = h[i].v1, s2[i] = h[i].v2
__global__ void compute_s_kernel(const float* __restrict__ h) {
    int warp = (blockIdx.x * blockDim.x + threadIdx.x) >> 5;
    int lane = threadIdx.x & 31;
    if (warp >= Nn) return;
    const float* hrow = h + (size_t)warp * FIN;
    float acc1 = 0.f, acc2 = 0.f;
#pragma unroll
    for (int k = lane; k < FIN; k += 32) {
        float x = hrow[k];
        acc1 = fmaf(x, g_v1[k], acc1);
        acc2 = fmaf(x, g_v2[k], acc2);
    }
#pragma unroll
    for (int o = 16; o; o >>= 1) {
        acc1 += __shfl_xor_sync(0xffffffffu, acc1, o);
        acc2 += __shfl_xor_sync(0xffffffffu, acc2, o);
    }
    if (lane == 0) {
        g_s1[warp] = acc1;
        g_s2[warp] = acc2;
    }
}

// Kernel 2b: global max of s2 (one block)
__global__ void max_s2_kernel() {
    __shared__ float red[32];
    int t = threadIdx.x;
    float m = -1e30f;
#pragma unroll
    for (int i = t; i < Nn; i += 1024)
        m = fmaxf(m, g_s2[i]);
#pragma unroll
    for (int o = 16; o; o >>= 1)
        m = fmaxf(m, __shfl_xor_sync(0xffffffffu, m, o));
    if ((t & 31) == 0) red[t >> 5] = m;
    __syncthreads();
    if (t < 32) {
        m = red[t];
#pragma unroll
        for (int o = 16; o; o >>= 1)
            m = fmaxf(m, __shfl_xor_sync(0xffffffffu, m, o));
        if (t == 0) g_s2max = m;
    }
}

// Kernel 3: one block per row. Single pass: stream adj (evict-first),
// exp against a per-row upper bound as data arrives (no max reduction),
// one sum reduction, streaming writes.
__global__ __launch_bounds__(512) void attn_softmax_kernel(
    const int* __restrict__ adj, float* __restrict__ out) {
    __shared__ float red[32];

    const int row = blockIdx.x;
    const int t = threadIdx.x;
    const int wid = t >> 5;
    const int lane = t & 31;

    const float s1 = g_s1[row];
    // upper bound on this row's scores: lrelu monotone => e <= lrelu(s1 + max s2)
    float ubx = s1 + g_s2max;
    const float ub = (ubx > 0.f) ? ubx : ALPHA * ubx;

    const int4* adjrow = reinterpret_cast<const int4*>(adj + (size_t)row * Nn);
    const float4* s2v4 = reinterpret_cast<const float4*>(g_s2);

    // Pass A: load adj + s2, exp immediately, local sum
    float4 pv[4];
    float lsum = 0.f;
#pragma unroll
    for (int k = 0; k < 4; k++) {
        int i4 = t + k * 512;
        int4 av = __ldcs(&adjrow[i4]);
        float4 sv = s2v4[i4];
        float e0 = s1 + sv.x; e0 = (e0 > 0.f) ? e0 : ALPHA * e0;
        float e1 = s1 + sv.y; e1 = (e1 > 0.f) ? e1 : ALPHA * e1;
        float e2 = s1 + sv.z; e2 = (e2 > 0.f) ? e2 : ALPHA * e2;
        float e3 = s1 + sv.w; e3 = (e3 > 0.f) ? e3 : ALPHA * e3;
        float p0 = (av.x > 0) ? __expf(e0 - ub) : 0.f;
        float p1 = (av.y > 0) ? __expf(e1 - ub) : 0.f;
        float p2 = (av.z > 0) ? __expf(e2 - ub) : 0.f;
        float p3 = (av.w > 0) ? __expf(e3 - ub) : 0.f;
        pv[k].x = p0; pv[k].y = p1; pv[k].z = p2; pv[k].w = p3;
        lsum += (p0 + p1) + (p2 + p3);
    }

    // Block sum reduction (single reduction in the whole kernel)
#pragma unroll
    for (int o = 16; o; o >>= 1)
        lsum += __shfl_xor_sync(0xffffffffu, lsum, o);
    if (lane == 0) red[wid] = lsum;
    __syncthreads();
    if (t < 32) {
        float s = (t < 16) ? red[t] : 0.f;
#pragma unroll
        for (int o = 16; o; o >>= 1)
            s += __shfl_xor_sync(0xffffffffu, s, o);
        if (t == 0) red[0] = s;
    }
    __syncthreads();
    const float total = red[0];
    // fully-masked row: reference softmax of constant row = uniform
    const bool empty = (total == 0.f);
    const float inv = empty ? 0.f : 1.0f / total;
    const float unif = 1.0f / (float)Nn;

    // Pass B: normalized write straight from registers (streaming stores)
    float4* orow = reinterpret_cast<float4*>(out + (size_t)row * Nn);
#pragma unroll
    for (int k = 0; k < 4; k++) {
        int i4 = t + k * 512;
        float4 v = pv[k];
        v.x = empty ? unif : v.x * inv;
        v.y = empty ? unif : v.y * inv;
        v.z = empty ? unif : v.z * inv;
        v.w = empty ? unif : v.w * inv;
        __stcs(&orow[i4], v);
    }
}

extern "C" void kernel_launch(void* const* d_in, const int* in_sizes, int n_in,
                              void* d_out, int out_size) {
    const float* h   = (const float*)d_in[0];
    const int*   adj = (const int*)d_in[1];
    const float* W   = (const float*)d_in[2];
    const float* a   = (const float*)d_in[3];
    float* out = (float*)d_out;

    compute_v_kernel<<<FIN / 8, 256>>>(W, a);      // warp per k, 64 blocks
    compute_s_kernel<<<Nn / 8, 256>>>(h);          // warp per row
    max_s2_kernel<<<1, 1024>>>();                  // global s2 max (scalar)
    attn_softmax_kernel<<<Nn, 512>>>(adj, out);
}